// round 6
// baseline (speedup 1.0000x reference)
#include <cuda_runtime.h>
#include <stdint.h>

// out[b,i,j,:] = pe[clamp(128 + j - i, 0, 256), :]  (B=4, S=512, D=128 fp32)
//
// HBM-write-bound (537 MB stores, measured floor ~7.2 TB/s). This variant
// uses sm_103a 256-bit vector ld/st: one warp covers TWO consecutive output
// rows (1 KB contiguous). Lane l: row j0 + (l>>4), bytes [(l&15)*32, +32).
// Halves STG instruction count / L1TEX tag traffic per byte while keeping
// the fully-contiguous store ordering that measured fastest.

__global__ __launch_bounds__(256) void relpos_v8(
    const char* __restrict__ pe,    // [512][512 B]
    char* __restrict__ out,         // [n_rows][512 B]
    int n_pairs)                    // n_rows / 2
{
    int gtid = blockIdx.x * blockDim.x + threadIdx.x;
    int p    = gtid >> 5;           // row-pair index
    int lane = gtid & 31;
    if (p >= n_pairs) return;

    int row0 = p << 1;              // even row; pair shares the same i
    int j = (row0 & 511) + (lane >> 4);
    int i = (row0 >> 9) & 511;

    int rel = 128 + j - i;
    rel = rel < 0 ? 0 : (rel > 256 ? 256 : rel);

    const char* src = pe  + rel * 512 + (lane & 15) * 32;
    char*       dst = out + (size_t)p * 1024 + lane * 32;

    float v0,v1,v2,v3,v4,v5,v6,v7;
    asm volatile("ld.global.nc.v8.f32 {%0,%1,%2,%3,%4,%5,%6,%7}, [%8];"
                 : "=f"(v0),"=f"(v1),"=f"(v2),"=f"(v3),
                   "=f"(v4),"=f"(v5),"=f"(v6),"=f"(v7)
                 : "l"(src));
    asm volatile("st.global.cs.v8.f32 [%0], {%1,%2,%3,%4,%5,%6,%7,%8};"
                 :: "l"(dst),
                    "f"(v0),"f"(v1),"f"(v2),"f"(v3),
                    "f"(v4),"f"(v5),"f"(v6),"f"(v7)
                 : "memory");
}

extern "C" void kernel_launch(void* const* d_in, const int* in_sizes, int n_in,
                              void* d_out, int out_size)
{
    // d_in[0] = x (int32 [B,512], shape-only), d_in[1] = pe (float32 [512,128])
    const char* pe = (const char*)d_in[1];
    char* out = (char*)d_out;

    int n_rows  = out_size >> 7;        // B*S*S = 1,048,576
    int n_pairs = n_rows >> 1;          // 524,288
    int n_threads = n_pairs * 32;
    int block = 256;
    int grid = (n_threads + block - 1) / block;

    relpos_v8<<<grid, block>>>(pe, out, n_pairs);
}

// round 7
// speedup vs baseline: 1.4493x; 1.4493x over previous
#include <cuda_runtime.h>
#include <stdint.h>

// out[b,i,j,:] = pe[clamp(128 + j - i, 0, 256), :]
// B=4, S=512, D=128, pe is [512,128] fp32 (only rows 0..256 referenced).
//
// One warp per output row of 128 floats: lane l handles floats [4l, 4l+4).
// pe working set = 257 * 512B -> L1-resident after warm-up; the kernel is
// bound purely by the 537 MB of HBM stores.
//
// Measured floor: 74.2 us = 7.2 TB/s store throughput (~90% of HBM3e spec).
// Verified against 5 alternatives (diagonal reuse, batch-fold, TMA bulk
// stores, L2-residency split, 256-bit stores) — none beat this fully
// contiguous warp->address STG.128 stream; DRAM-active is the binding
// resource at ~80% regardless of issue mechanism.

__global__ __launch_bounds__(256) void relpos_kernel(
    const float4* __restrict__ pe,   // [512][32] float4
    float4* __restrict__ out,        // [n_rows][32] float4
    int n_rows)                      // B*S*S
{
    int gtid = blockIdx.x * blockDim.x + threadIdx.x;
    int warp = gtid >> 5;
    int lane = gtid & 31;
    if (warp >= n_rows) return;

    // warp -> (b, i, j); b unused (broadcast), layout row-major [B,S,S,D]
    int j = warp & 511;
    int i = (warp >> 9) & 511;

    int rel = 128 + j - i;
    rel = rel < 0 ? 0 : (rel > 256 ? 256 : rel);

    // coalesced 512B row read (L1-resident) + coalesced 512B row write
    out[(size_t)warp * 32 + lane] = pe[rel * 32 + lane];
}

extern "C" void kernel_launch(void* const* d_in, const int* in_sizes, int n_in,
                              void* d_out, int out_size)
{
    // d_in[0] = x (int32 [B,512], shape-only), d_in[1] = pe (float32 [512,128])
    const float4* pe = (const float4*)d_in[1];
    float4* out = (float4*)d_out;

    int n_rows = out_size >> 7;           // out_size / 128 = B*S*S
    int n_threads = n_rows * 32;
    int block = 256;
    int grid = (n_threads + block - 1) / block;

    relpos_kernel<<<grid, block>>>(pe, out, n_rows);
}